// round 5
// baseline (speedup 1.0000x reference)
#include <cuda_runtime.h>
#include <stdint.h>
#include <math.h>

#define NODES 262144
#define EDGES 2097152

// Scratch (device globals — no runtime allocation allowed)
__device__ __align__(16) float g_y0[NODES * 8];   // dinv * x           (layer1 gather src)
__device__ __align__(16) float g_y1[NODES * 16];  // dinv * relu(h1)    (layer2 gather src)
__device__ __align__(16) float g_y2[NODES * 32];  // dinv * relu(h2)    (layer3 gather src)
__device__ int   g_cnt[NODES];
__device__ int   g_row[NODES];
__device__ int   g_cur[NODES];
__device__ float g_dinv[NODES];
__device__ int   g_col[EDGES];
__device__ int   g_total;          // global bucket cursor

// ---------------- f32x2 packed-FMA helpers (sm_103a FFMA2) ----------------
__device__ __forceinline__ unsigned long long pack2(float lo, float hi) {
    unsigned long long r;
    asm("mov.b64 %0, {%1, %2};" : "=l"(r) : "f"(lo), "f"(hi));
    return r;
}
__device__ __forceinline__ void unpack2(unsigned long long v, float& lo, float& hi) {
    asm("mov.b64 {%0, %1}, %2;" : "=f"(lo), "=f"(hi) : "l"(v));
}
__device__ __forceinline__ void ffma2(unsigned long long& d, unsigned long long a,
                                      unsigned long long b) {
    asm("fma.rn.f32x2 %0, %1, %2, %0;" : "+l"(d) : "l"(a), "l"(b));
}

// ---------------- CSR build ----------------

__global__ void k_hist4(const int* __restrict__ dst, int e4) {
    int i = blockIdx.x * blockDim.x + threadIdx.x;
    if (i < e4) {
        int4 d = ((const int4*)dst)[i];
        atomicAdd(&g_cnt[d.x], 1);
        atomicAdd(&g_cnt[d.y], 1);
        atomicAdd(&g_cnt[d.z], 1);
        atomicAdd(&g_cnt[d.w], 1);
    }
}

__global__ void k_hist(const int* __restrict__ dst, int e) {
    int i = blockIdx.x * blockDim.x + threadIdx.x;
    if (i < e) atomicAdd(&g_cnt[dst[i]], 1);
}

// Allocate per-node CSR ranges via warp-aggregated atomic (bucket order is irrelevant),
// finalize dinv, and emit y0 = dinv * x.
__global__ void k_fin(const float* __restrict__ x, int n) {
    int i = blockIdx.x * blockDim.x + threadIdx.x;
    int lane = threadIdx.x & 31;
    int c = (i < n) ? g_cnt[i] : 0;

    // warp inclusive prefix sum of c
    int pfx = c;
    #pragma unroll
    for (int off = 1; off < 32; off <<= 1) {
        int v = __shfl_up_sync(0xffffffffu, pfx, off);
        if (lane >= off) pfx += v;
    }
    int tot = __shfl_sync(0xffffffffu, pfx, 31);
    int base = 0;
    if (lane == 31) base = atomicAdd(&g_total, tot);
    base = __shfl_sync(0xffffffffu, base, 31);
    int r = base + pfx - c;          // exclusive offset for this node

    if (i < n) {
        g_row[i] = r;
        g_cur[i] = r;
        float di = rsqrtf((float)(c + 1));
        g_dinv[i] = di;
        float4 a = ((const float4*)x)[i * 2];
        float4 b = ((const float4*)x)[i * 2 + 1];
        a.x *= di; a.y *= di; a.z *= di; a.w *= di;
        b.x *= di; b.y *= di; b.z *= di; b.w *= di;
        ((float4*)g_y0)[i * 2]     = a;
        ((float4*)g_y0)[i * 2 + 1] = b;
    }
}

__global__ void k_scatter4(const int* __restrict__ src, const int* __restrict__ dst, int e4) {
    int i = blockIdx.x * blockDim.x + threadIdx.x;
    if (i < e4) {
        int4 s = ((const int4*)src)[i];
        int4 d = ((const int4*)dst)[i];
        g_col[atomicAdd(&g_cur[d.x], 1)] = s.x;
        g_col[atomicAdd(&g_cur[d.y], 1)] = s.y;
        g_col[atomicAdd(&g_cur[d.z], 1)] = s.z;
        g_col[atomicAdd(&g_cur[d.w], 1)] = s.w;
    }
}

__global__ void k_scatter(const int* __restrict__ src, const int* __restrict__ dst, int e) {
    int i = blockIdx.x * blockDim.x + threadIdx.x;
    if (i < e) {
        int d = dst[i];
        int p = atomicAdd(&g_cur[d], 1);
        g_col[p] = src[i];
    }
}

// ---------------- layer 1: agg@8 -> GEMM 8->16 -> relu -> scale (warp per node) ----------------
__global__ void k_layer1(const float* __restrict__ yin, const float* __restrict__ W,
                         const float* __restrict__ b, float* __restrict__ yout, int n) {
    __shared__ float sW[8 * 16];
    if (threadIdx.x < 128) sW[threadIdx.x] = W[threadIdx.x];
    __syncthreads();

    int node = (blockIdx.x * blockDim.x + threadIdx.x) >> 5;
    int lane = threadIdx.x & 31;
    if (node >= n) return;

    int start = g_row[node];
    int cnt   = g_cnt[node];
    float di  = g_dinv[node];

    int f  = lane & 7;
    int eo = lane >> 3;                 // 4 edge groups

    float acc = (lane < 8) ? yin[(size_t)node * 8 + lane] : 0.f;
    int e = eo;
    for (; e + 4 < cnt; e += 8) {
        int s0 = g_col[start + e];
        int s1 = g_col[start + e + 4];
        acc += yin[(size_t)s0 * 8 + f] + yin[(size_t)s1 * 8 + f];
    }
    if (e < cnt) acc += yin[(size_t)g_col[start + e] * 8 + f];

    acc += __shfl_xor_sync(0xffffffffu, acc, 8);
    acc += __shfl_xor_sync(0xffffffffu, acc, 16);
    acc *= di;                          // lane f holds agg[f], replicated over groups

    // split-k GEMM: lane -> (j = lane%16, half = lane/16 handles k in [4h, 4h+4))
    int j = lane & 15, half = lane >> 4;
    float o = 0.f;
    #pragma unroll
    for (int kk = 0; kk < 4; kk++) {
        int k = half * 4 + kk;
        o += __shfl_sync(0xffffffffu, acc, k) * sW[k * 16 + j];
    }
    o += __shfl_xor_sync(0xffffffffu, o, 16);
    if (lane < 16)
        yout[(size_t)node * 16 + lane] = fmaxf(o + b[lane], 0.f) * di;
}

// ---------------- layer 2: agg@16 -> GEMM 16->32 -> relu -> scale (warp per node) -------------
__global__ void k_layer2(const float* __restrict__ yin, const float* __restrict__ W,
                         const float* __restrict__ b, float* __restrict__ yout, int n) {
    __shared__ float sW[16 * 32];
    for (int i = threadIdx.x; i < 512; i += blockDim.x) sW[i] = W[i];
    __syncthreads();

    int node = (blockIdx.x * blockDim.x + threadIdx.x) >> 5;
    int lane = threadIdx.x & 31;
    if (node >= n) return;

    int start = g_row[node];
    int cnt   = g_cnt[node];
    float di  = g_dinv[node];

    int f  = lane & 15;
    int eo = lane >> 4;                 // 2 edge groups

    float acc = (lane < 16) ? yin[(size_t)node * 16 + lane] : 0.f;
    int e = eo;
    for (; e + 2 < cnt; e += 4) {
        int s0 = g_col[start + e];
        int s1 = g_col[start + e + 2];
        acc += yin[(size_t)s0 * 16 + f] + yin[(size_t)s1 * 16 + f];
    }
    if (e < cnt) acc += yin[(size_t)g_col[start + e] * 16 + f];

    acc += __shfl_xor_sync(0xffffffffu, acc, 16);
    acc *= di;

    float o = b[lane];
    #pragma unroll
    for (int k = 0; k < 16; k++)
        o += __shfl_sync(0xffffffffu, acc, k) * sW[k * 32 + lane];
    yout[(size_t)node * 32 + lane] = fmaxf(o, 0.f) * di;
}

// ---------------- layer 3 + FC: block of 256 handles 32 nodes (FFMA2 GEMMs) ----------------
__global__ __launch_bounds__(256) void k_l3fc(
        const float* __restrict__ yin, const float* __restrict__ W3,
        const float* __restrict__ b3, const float* __restrict__ Wfc,
        const float* __restrict__ bfc, float* __restrict__ out, int n) {
    __shared__ float sW3[32 * 64];      // 8 KB   [k][j]
    __shared__ float sWfc[64 * 64];     // 16 KB  [k][j]
    __shared__ float sAgg[32][33];      // [node][k]
    __shared__ float sH[32][65];        // [node][k]

    int tid = threadIdx.x;
    for (int i = tid; i < 32 * 64; i += 256) sW3[i] = W3[i];
    for (int i = tid; i < 64 * 64; i += 256) sWfc[i] = Wfc[i];

    int node0 = blockIdx.x * 32;
    int warp  = tid >> 5;
    int lane  = tid & 31;

    // ---- aggregation: each warp handles 4 nodes; lane = feature ----
    #pragma unroll
    for (int r = 0; r < 4; r++) {
        int ln = warp * 4 + r;
        int node = node0 + ln;
        float acc = 0.f;
        if (node < n) {
            int start = g_row[node];
            int cnt   = g_cnt[node];
            float di  = g_dinv[node];
            acc = yin[(size_t)node * 32 + lane];
            int e = 0;
            for (; e + 3 < cnt; e += 4) {
                int s0 = g_col[start + e];
                int s1 = g_col[start + e + 1];
                int s2 = g_col[start + e + 2];
                int s3 = g_col[start + e + 3];
                acc += yin[(size_t)s0 * 32 + lane] + yin[(size_t)s1 * 32 + lane]
                     + yin[(size_t)s2 * 32 + lane] + yin[(size_t)s3 * 32 + lane];
            }
            for (; e < cnt; e++)
                acc += yin[(size_t)g_col[start + e] * 32 + lane];
            acc *= di;
        }
        sAgg[ln][lane] = acc;
    }
    __syncthreads();

    int r0 = (tid >> 4) * 2;            // 2 rows per thread
    int c0 = (tid & 15) * 4;            // 4 cols per thread

    // ---- GEMM1: H[32x64] = relu(AGG[32x32] @ W3 + b3), packed f32x2 ----
    unsigned long long acc0[2], acc1[2];
    {
        float4 bv = *(const float4*)&b3[c0];
        acc0[0] = pack2(bv.x, bv.y); acc0[1] = pack2(bv.z, bv.w);
        acc1[0] = acc0[0];           acc1[1] = acc0[1];
    }
    #pragma unroll
    for (int k = 0; k < 32; k++) {
        unsigned long long a0 = pack2(sAgg[r0][k],     sAgg[r0][k]);
        unsigned long long a1 = pack2(sAgg[r0 + 1][k], sAgg[r0 + 1][k]);
        const unsigned long long* wp = (const unsigned long long*)&sW3[k * 64 + c0];
        unsigned long long w01 = wp[0], w23 = wp[1];
        ffma2(acc0[0], a0, w01); ffma2(acc0[1], a0, w23);
        ffma2(acc1[0], a1, w01); ffma2(acc1[1], a1, w23);
    }
    {
        float v0, v1, v2, v3;
        unpack2(acc0[0], v0, v1); unpack2(acc0[1], v2, v3);
        sH[r0][c0]     = fmaxf(v0, 0.f); sH[r0][c0 + 1] = fmaxf(v1, 0.f);
        sH[r0][c0 + 2] = fmaxf(v2, 0.f); sH[r0][c0 + 3] = fmaxf(v3, 0.f);
        unpack2(acc1[0], v0, v1); unpack2(acc1[1], v2, v3);
        sH[r0 + 1][c0]     = fmaxf(v0, 0.f); sH[r0 + 1][c0 + 1] = fmaxf(v1, 0.f);
        sH[r0 + 1][c0 + 2] = fmaxf(v2, 0.f); sH[r0 + 1][c0 + 3] = fmaxf(v3, 0.f);
    }
    __syncthreads();

    // ---- GEMM2: OUT[32x64] = H[32x64] @ Wfc + bfc, packed f32x2 ----
    {
        float4 bv = *(const float4*)&bfc[c0];
        acc0[0] = pack2(bv.x, bv.y); acc0[1] = pack2(bv.z, bv.w);
        acc1[0] = acc0[0];           acc1[1] = acc0[1];
    }
    #pragma unroll
    for (int k = 0; k < 64; k++) {
        unsigned long long a0 = pack2(sH[r0][k],     sH[r0][k]);
        unsigned long long a1 = pack2(sH[r0 + 1][k], sH[r0 + 1][k]);
        const unsigned long long* wp = (const unsigned long long*)&sWfc[k * 64 + c0];
        unsigned long long w01 = wp[0], w23 = wp[1];
        ffma2(acc0[0], a0, w01); ffma2(acc0[1], a0, w23);
        ffma2(acc1[0], a1, w01); ffma2(acc1[1], a1, w23);
    }
    int nodeA = node0 + r0, nodeB = node0 + r0 + 1;
    if (nodeA < n) {
        float4 o;
        unpack2(acc0[0], o.x, o.y); unpack2(acc0[1], o.z, o.w);
        *(float4*)&out[(size_t)nodeA * 64 + c0] = o;
    }
    if (nodeB < n) {
        float4 o;
        unpack2(acc1[0], o.x, o.y); unpack2(acc1[1], o.z, o.w);
        *(float4*)&out[(size_t)nodeB * 64 + c0] = o;
    }
}

// ---------------- launch ----------------

extern "C" void kernel_launch(void* const* d_in, const int* in_sizes, int n_in,
                              void* d_out, int out_size) {
    const float* x   = (const float*)d_in[0];
    const float* W1  = (const float*)d_in[1];
    const float* b1  = (const float*)d_in[2];
    const float* W2  = (const float*)d_in[3];
    const float* b2  = (const float*)d_in[4];
    const float* W3  = (const float*)d_in[5];
    const float* b3  = (const float*)d_in[6];
    const float* Wfc = (const float*)d_in[7];
    const float* bfc = (const float*)d_in[8];
    const int*   ei  = (const int*)d_in[9];

    int n = in_sizes[0] / 8;
    int e = in_sizes[9] / 2;
    const int* src = ei;
    const int* dst = ei + e;
    float* out = (float*)d_out;

    float *y0, *y1, *y2;
    int *cntp, *totp;
    cudaGetSymbolAddress((void**)&y0, g_y0);
    cudaGetSymbolAddress((void**)&y1, g_y1);
    cudaGetSymbolAddress((void**)&y2, g_y2);
    cudaGetSymbolAddress((void**)&cntp, g_cnt);
    cudaGetSymbolAddress((void**)&totp, g_total);

    cudaMemsetAsync(cntp, 0, (size_t)n * sizeof(int));
    cudaMemsetAsync(totp, 0, sizeof(int));

    bool vec = ((e & 3) == 0) && ((((size_t)dst) & 15) == 0) && ((((size_t)src) & 15) == 0);
    if (vec) {
        int e4 = e / 4;
        k_hist4<<<(e4 + 255) / 256, 256>>>(dst, e4);
    } else {
        k_hist<<<(e + 255) / 256, 256>>>(dst, e);
    }

    k_fin<<<(n + 255) / 256, 256>>>(x, n);

    if (vec) {
        int e4 = e / 4;
        k_scatter4<<<(e4 + 255) / 256, 256>>>(src, dst, e4);
    } else {
        k_scatter<<<(e + 255) / 256, 256>>>(src, dst, e);
    }

    int wgrid = (n * 32 + 255) / 256;
    k_layer1<<<wgrid, 256>>>(y0, W1, b1, y1, n);   // profiled slot (#4)
    k_layer2<<<wgrid, 256>>>(y1, W2, b2, y2, n);
    k_l3fc<<<(n + 31) / 32, 256>>>(y2, W3, b3, Wfc, bfc, out, n);
}

// round 6
// speedup vs baseline: 1.2733x; 1.2733x over previous
#include <cuda_runtime.h>
#include <stdint.h>
#include <math.h>

#define NODES 262144
#define EDGES 2097152

__device__ __align__(16) float g_y0[NODES * 8];   // dinv * x           (layer1 gather src)
__device__ __align__(16) float g_y1[NODES * 16];  // dinv * relu(h1)    (layer2 gather src)
__device__ __align__(16) float g_y2[NODES * 32];  // dinv * relu(h2)    (layer3 gather src)
__device__ int   g_cnt[NODES];
__device__ int   g_row[NODES];
__device__ int   g_cur[NODES];
__device__ float g_dinv[NODES];
__device__ int   g_col[EDGES];
__device__ int   g_bsum[512];

// ---------------- CSR build (ordered scan -> coalesced g_col reads) ----------------

__global__ void k_hist(const int* __restrict__ dst, int e) {
    int i = blockIdx.x * blockDim.x + threadIdx.x;
    if (i < e) atomicAdd(&g_cnt[dst[i]], 1);
}

__global__ void k_scan1(int n) {
    __shared__ int s[512];
    int t = threadIdx.x;
    int idx = blockIdx.x * 512 + t;
    int v = (idx < n) ? g_cnt[idx] : 0;
    s[t] = v;
    __syncthreads();
    #pragma unroll
    for (int off = 1; off < 512; off <<= 1) {
        int a = (t >= off) ? s[t - off] : 0;
        __syncthreads();
        s[t] += a;
        __syncthreads();
    }
    if (idx < n) g_row[idx] = s[t] - v;
    if (t == 511) g_bsum[blockIdx.x] = s[511];
}

// block-sum prefix (redundant per-block reduction) + finalize + y0 = dinv*x
__global__ void k_scan2fin(const float* __restrict__ x, int n) {
    __shared__ int s[512];
    int b = blockIdx.x, t = threadIdx.x;
    s[t] = (t < b) ? g_bsum[t] : 0;
    __syncthreads();
    #pragma unroll
    for (int off = 256; off > 0; off >>= 1) {
        if (t < off) s[t] += s[t + off];
        __syncthreads();
    }
    int offset = s[0];
    int i = b * 512 + t;
    if (i < n) {
        int r = g_row[i] + offset;
        g_row[i] = r;
        g_cur[i] = r;
        float di = rsqrtf((float)(g_cnt[i] + 1));
        g_dinv[i] = di;
        float4 a = ((const float4*)x)[i * 2];
        float4 c = ((const float4*)x)[i * 2 + 1];
        a.x *= di; a.y *= di; a.z *= di; a.w *= di;
        c.x *= di; c.y *= di; c.z *= di; c.w *= di;
        ((float4*)g_y0)[i * 2]     = a;
        ((float4*)g_y0)[i * 2 + 1] = c;
    }
}

__global__ void k_scatter(const int* __restrict__ src, const int* __restrict__ dst, int e) {
    int i = blockIdx.x * blockDim.x + threadIdx.x;
    if (i < e) {
        int d = dst[i];
        int p = atomicAdd(&g_cur[d], 1);
        g_col[p] = src[i];
    }
}

// ---------------- layer 1: 128 nodes/block; agg (2 lanes/node) + GEMM 8->16 ----------------
__global__ __launch_bounds__(256) void k_layer1(const float* __restrict__ yin,
                                                const float* __restrict__ W,
                                                const float* __restrict__ b,
                                                float* __restrict__ yout, int n) {
    __shared__ float sW[8 * 16];          // [k][j]
    __shared__ float sAgg[128][12];       // 16B-aligned rows, bank-spread stride
    __shared__ float sDinv[128];

    int tid = threadIdx.x;
    if (tid < 128) sW[tid] = W[tid];

    int node0 = blockIdx.x * 128;
    int warp = tid >> 5, lane = tid & 31;
    int ln = warp * 16 + (lane >> 1);     // local node 0..127
    int h  = lane & 1;                    // feature half (float4)
    int node = node0 + ln;

    const float4* yv = (const float4*)yin;
    float4 acc = make_float4(0.f, 0.f, 0.f, 0.f);
    float di = 0.f;
    if (node < n) {
        int start = g_row[node];
        int cnt   = g_cnt[node];
        di = g_dinv[node];
        acc = yv[(size_t)node * 2 + h];   // self term
        int e = 0;
        for (; e + 1 < cnt; e += 2) {
            int s0 = g_col[start + e];
            int s1 = g_col[start + e + 1];
            float4 v0 = yv[(size_t)s0 * 2 + h];
            float4 v1 = yv[(size_t)s1 * 2 + h];
            acc.x += v0.x + v1.x; acc.y += v0.y + v1.y;
            acc.z += v0.z + v1.z; acc.w += v0.w + v1.w;
        }
        if (e < cnt) {
            float4 v = yv[(size_t)g_col[start + e] * 2 + h];
            acc.x += v.x; acc.y += v.y; acc.z += v.z; acc.w += v.w;
        }
        acc.x *= di; acc.y *= di; acc.z *= di; acc.w *= di;
    }
    *(float4*)&sAgg[ln][h * 4] = acc;
    if (h == 0) sDinv[ln] = di;
    __syncthreads();

    // GEMM: thread -> (node = tid>>1, half = tid&1) computes 8 outputs
    int nl = tid >> 1, j0 = (tid & 1) * 8;
    int onode = node0 + nl;
    if (onode >= n) return;
    float o[8];
    #pragma unroll
    for (int j = 0; j < 8; j++) o[j] = b[j0 + j];
    #pragma unroll
    for (int k = 0; k < 8; k++) {
        float a = sAgg[nl][k];
        #pragma unroll
        for (int j = 0; j < 8; j++) o[j] += a * sW[k * 16 + j0 + j];
    }
    float d2 = sDinv[nl];
    float4 o0, o1;
    o0.x = fmaxf(o[0], 0.f) * d2; o0.y = fmaxf(o[1], 0.f) * d2;
    o0.z = fmaxf(o[2], 0.f) * d2; o0.w = fmaxf(o[3], 0.f) * d2;
    o1.x = fmaxf(o[4], 0.f) * d2; o1.y = fmaxf(o[5], 0.f) * d2;
    o1.z = fmaxf(o[6], 0.f) * d2; o1.w = fmaxf(o[7], 0.f) * d2;
    float4* op = (float4*)&yout[(size_t)onode * 16 + j0];
    op[0] = o0; op[1] = o1;
}

// ---------------- layer 2: 64 nodes/block; agg (4 lanes/node) + GEMM 16->32 ----------------
__global__ __launch_bounds__(256) void k_layer2(const float* __restrict__ yin,
                                                const float* __restrict__ W,
                                                const float* __restrict__ b,
                                                float* __restrict__ yout, int n) {
    __shared__ float sW[16 * 32];         // [k][j]
    __shared__ float sAgg[64][20];        // 16B-aligned rows, bank-spread stride
    __shared__ float sDinv[64];

    int tid = threadIdx.x;
    for (int i = tid; i < 512; i += 256) sW[i] = W[i];

    int node0 = blockIdx.x * 64;
    int warp = tid >> 5, lane = tid & 31;
    int ln = warp * 8 + (lane >> 2);      // local node 0..63
    int q  = lane & 3;                    // feature quarter (float4)
    int node = node0 + ln;

    const float4* yv = (const float4*)yin;
    float4 acc = make_float4(0.f, 0.f, 0.f, 0.f);
    float di = 0.f;
    if (node < n) {
        int start = g_row[node];
        int cnt   = g_cnt[node];
        di = g_dinv[node];
        acc = yv[(size_t)node * 4 + q];
        int e = 0;
        for (; e + 1 < cnt; e += 2) {
            int s0 = g_col[start + e];
            int s1 = g_col[start + e + 1];
            float4 v0 = yv[(size_t)s0 * 4 + q];
            float4 v1 = yv[(size_t)s1 * 4 + q];
            acc.x += v0.x + v1.x; acc.y += v0.y + v1.y;
            acc.z += v0.z + v1.z; acc.w += v0.w + v1.w;
        }
        if (e < cnt) {
            float4 v = yv[(size_t)g_col[start + e] * 4 + q];
            acc.x += v.x; acc.y += v.y; acc.z += v.z; acc.w += v.w;
        }
        acc.x *= di; acc.y *= di; acc.z *= di; acc.w *= di;
    }
    *(float4*)&sAgg[ln][q * 4] = acc;
    if (q == 0) sDinv[ln] = di;
    __syncthreads();

    // GEMM: thread -> (node = tid>>2, quarter = tid&3) computes 8 outputs
    int nl = tid >> 2, j0 = (tid & 3) * 8;
    int onode = node0 + nl;
    if (onode >= n) return;
    float o[8];
    #pragma unroll
    for (int j = 0; j < 8; j++) o[j] = b[j0 + j];
    #pragma unroll
    for (int k = 0; k < 16; k++) {
        float a = sAgg[nl][k];
        #pragma unroll
        for (int j = 0; j < 8; j++) o[j] += a * sW[k * 32 + j0 + j];
    }
    float d2 = sDinv[nl];
    float4 o0, o1;
    o0.x = fmaxf(o[0], 0.f) * d2; o0.y = fmaxf(o[1], 0.f) * d2;
    o0.z = fmaxf(o[2], 0.f) * d2; o0.w = fmaxf(o[3], 0.f) * d2;
    o1.x = fmaxf(o[4], 0.f) * d2; o1.y = fmaxf(o[5], 0.f) * d2;
    o1.z = fmaxf(o[6], 0.f) * d2; o1.w = fmaxf(o[7], 0.f) * d2;
    float4* op = (float4*)&yout[(size_t)onode * 32 + j0];
    op[0] = o0; op[1] = o1;
}

// ---------------- layer 3 + FC: block of 256 handles 32 nodes (R3 float4 GEMMs) ----------------
__global__ __launch_bounds__(256) void k_l3fc(
        const float* __restrict__ yin, const float* __restrict__ W3,
        const float* __restrict__ b3, const float* __restrict__ Wfc,
        const float* __restrict__ bfc, float* __restrict__ out, int n) {
    __shared__ float sW3[32 * 64];      // [k][j]
    __shared__ float sWfc[64 * 64];     // [k][j]
    __shared__ float sAgg[32][33];
    __shared__ float sH[32][65];

    int tid = threadIdx.x;
    for (int i = tid; i < 32 * 64; i += 256) sW3[i] = W3[i];
    for (int i = tid; i < 64 * 64; i += 256) sWfc[i] = Wfc[i];

    int node0 = blockIdx.x * 32;
    int warp  = tid >> 5;
    int lane  = tid & 31;

    #pragma unroll
    for (int r = 0; r < 4; r++) {
        int ln = warp * 4 + r;
        int node = node0 + ln;
        float acc = 0.f;
        if (node < n) {
            int start = g_row[node];
            int cnt   = g_cnt[node];
            float di  = g_dinv[node];
            acc = yin[(size_t)node * 32 + lane];
            int e = 0;
            for (; e + 3 < cnt; e += 4) {
                int s0 = g_col[start + e];
                int s1 = g_col[start + e + 1];
                int s2 = g_col[start + e + 2];
                int s3 = g_col[start + e + 3];
                acc += yin[(size_t)s0 * 32 + lane] + yin[(size_t)s1 * 32 + lane]
                     + yin[(size_t)s2 * 32 + lane] + yin[(size_t)s3 * 32 + lane];
            }
            for (; e < cnt; e++)
                acc += yin[(size_t)g_col[start + e] * 32 + lane];
            acc *= di;
        }
        sAgg[ln][lane] = acc;
    }
    __syncthreads();

    int r0 = (tid >> 4) * 2;
    int c0 = (tid & 15) * 4;
    float acc0[4], acc1[4];
    {
        float4 bv = *(const float4*)&b3[c0];
        acc0[0] = bv.x; acc0[1] = bv.y; acc0[2] = bv.z; acc0[3] = bv.w;
        acc1[0] = bv.x; acc1[1] = bv.y; acc1[2] = bv.z; acc1[3] = bv.w;
    }
    #pragma unroll
    for (int k = 0; k < 32; k++) {
        float a0 = sAgg[r0][k];
        float a1 = sAgg[r0 + 1][k];
        float4 w = *(const float4*)&sW3[k * 64 + c0];
        acc0[0] += a0 * w.x; acc0[1] += a0 * w.y; acc0[2] += a0 * w.z; acc0[3] += a0 * w.w;
        acc1[0] += a1 * w.x; acc1[1] += a1 * w.y; acc1[2] += a1 * w.z; acc1[3] += a1 * w.w;
    }
    #pragma unroll
    for (int j = 0; j < 4; j++) {
        sH[r0][c0 + j]     = fmaxf(acc0[j], 0.f);
        sH[r0 + 1][c0 + j] = fmaxf(acc1[j], 0.f);
    }
    __syncthreads();

    {
        float4 bv = *(const float4*)&bfc[c0];
        acc0[0] = bv.x; acc0[1] = bv.y; acc0[2] = bv.z; acc0[3] = bv.w;
        acc1[0] = bv.x; acc1[1] = bv.y; acc1[2] = bv.z; acc1[3] = bv.w;
    }
    #pragma unroll
    for (int k = 0; k < 64; k++) {
        float a0 = sH[r0][k];
        float a1 = sH[r0 + 1][k];
        float4 w = *(const float4*)&sWfc[k * 64 + c0];
        acc0[0] += a0 * w.x; acc0[1] += a0 * w.y; acc0[2] += a0 * w.z; acc0[3] += a0 * w.w;
        acc1[0] += a1 * w.x; acc1[1] += a1 * w.y; acc1[2] += a1 * w.z; acc1[3] += a1 * w.w;
    }
    int nodeA = node0 + r0, nodeB = node0 + r0 + 1;
    if (nodeA < n) {
        float4 o; o.x = acc0[0]; o.y = acc0[1]; o.z = acc0[2]; o.w = acc0[3];
        *(float4*)&out[(size_t)nodeA * 64 + c0] = o;
    }
    if (nodeB < n) {
        float4 o; o.x = acc1[0]; o.y = acc1[1]; o.z = acc1[2]; o.w = acc1[3];
        *(float4*)&out[(size_t)nodeB * 64 + c0] = o;
    }
}

// ---------------- launch ----------------

extern "C" void kernel_launch(void* const* d_in, const int* in_sizes, int n_in,
                              void* d_out, int out_size) {
    const float* x   = (const float*)d_in[0];
    const float* W1  = (const float*)d_in[1];
    const float* b1  = (const float*)d_in[2];
    const float* W2  = (const float*)d_in[3];
    const float* b2  = (const float*)d_in[4];
    const float* W3  = (const float*)d_in[5];
    const float* b3  = (const float*)d_in[6];
    const float* Wfc = (const float*)d_in[7];
    const float* bfc = (const float*)d_in[8];
    const int*   ei  = (const int*)d_in[9];

    int n = in_sizes[0] / 8;
    int e = in_sizes[9] / 2;
    const int* src = ei;
    const int* dst = ei + e;
    float* out = (float*)d_out;

    float *y0, *y1, *y2;
    int* cntp;
    cudaGetSymbolAddress((void**)&y0, g_y0);
    cudaGetSymbolAddress((void**)&y1, g_y1);
    cudaGetSymbolAddress((void**)&y2, g_y2);
    cudaGetSymbolAddress((void**)&cntp, g_cnt);

    cudaMemsetAsync(cntp, 0, (size_t)n * sizeof(int));

    k_hist<<<(e + 255) / 256, 256>>>(dst, e);
    k_scan1<<<(n + 511) / 512, 512>>>(n);
    k_scan2fin<<<(n + 511) / 512, 512>>>(x, n);
    k_scatter<<<(e + 255) / 256, 256>>>(src, dst, e);

    k_layer1<<<(n + 127) / 128, 256>>>(y0, W1, b1, y1, n);   // profiled slot
    k_layer2<<<(n + 63) / 64, 256>>>(y1, W2, b2, y2, n);
    k_l3fc<<<(n + 31) / 32, 256>>>(y2, W3, b3, Wfc, bfc, out, n);
}